// round 13
// baseline (speedup 1.0000x reference)
#include <cuda_runtime.h>
#include <cstdint>

#define S_LEN    2048
#define NBATCH   64
#define DIN      512
#define HDIM     512
#define NCTA     128

// ---- 1 GB x-projection scratch: xp[t][ct][b][16] ----
__device__ float g_xp[(size_t)S_LEN * 128 * 64 * 16];

// monotonic grid-barrier counter (64-bit: no wrap across replays)
__device__ unsigned long long g_cnt = 0;

__device__ __forceinline__ float fast_sigmoid(float x) {
    return 1.0f / (1.0f + __expf(-x));
}
__device__ __forceinline__ float fast_tanh(float x) {
    float ax = fabsf(x);
    float e  = __expf(-2.0f * ax);
    return copysignf((1.0f - e) / (1.0f + e), x);
}
__device__ __forceinline__ unsigned to_tf32(float f) {
    unsigned r;
    asm("cvt.rna.tf32.f32 %0, %1;" : "=r"(r) : "f"(f));
    return r;
}
__device__ __forceinline__ void mma_tf32(float* c, unsigned a0, unsigned a1,
                                         unsigned a2, unsigned a3,
                                         unsigned b0, unsigned b1) {
    asm("mma.sync.aligned.m16n8k8.row.col.f32.tf32.tf32.f32 "
        "{%0,%1,%2,%3}, {%4,%5,%6,%7}, {%8,%9}, {%0,%1,%2,%3};"
        : "+f"(c[0]), "+f"(c[1]), "+f"(c[2]), "+f"(c[3])
        : "r"(a0), "r"(a1), "r"(a2), "r"(a3), "r"(b0), "r"(b1));
}
// release-arrive / acquire-poll (PTX memory model: STG -> bar.sync -> release
// by tid0 happens-before an acquiring reader that observes the new count)
__device__ __forceinline__ void bar_arrive_release(unsigned long long* p) {
    asm volatile("red.release.gpu.global.add.u64 [%0], 1;" :: "l"(p) : "memory");
}
__device__ __forceinline__ unsigned long long ld_acquire(unsigned long long* p) {
    unsigned long long v;
    asm volatile("ld.acquire.gpu.global.u64 %0, [%1];" : "=l"(v) : "l"(p) : "memory");
    return v;
}

// gate-row scatter: n in [0,2048) -> W row
__device__ __forceinline__ int grow_of(int n) {
    return (n & 3) * HDIM + (n >> 4) * 4 + ((n >> 2) & 3);
}

// ======================= Phase 1: xp = x @ W_ih^T =======================
// C[M=131072, N=2048], K=512. CTA tile 128x64; K chunks of 64 with a
// register-prefetch pipeline (LDG ch+1 overlaps HMMA on ch).
__global__ __launch_bounds__(256, 2)
void lstm_xproj(const float* __restrict__ x, const float* __restrict__ Wih)
{
    extern __shared__ float sm1[];
    float* At = sm1;              // 128 x 68
    float* Bt = sm1 + 128 * 68;   // 64 x 68

    const int tid  = threadIdx.x;
    const int lane = tid & 31;
    const int w    = tid >> 5;
    const int mw   = w & 3;                 // 32-row block
    const int nw   = w >> 2;                // 32-col block
    const int ntile = blockIdx.x & 31;      // ntile-fastest: x reused in L2
    const int mtile = blockIdx.x >> 5;
    const int Mb = mtile * 128, Nb = ntile * 64;

    const int lb = tid >> 2;                // 0..63
    const int kc = (tid & 3) * 4;

    float acc[2][4][4];
#pragma unroll
    for (int a = 0; a < 2; ++a)
#pragma unroll
        for (int b = 0; b < 4; ++b)
#pragma unroll
            for (int q = 0; q < 4; ++q) acc[a][b][q] = 0.f;

    float4 pa[8], pb[4];

#define LOADX(CH) do {                                                     \
        const float* _x0 = x + (size_t)(Mb + lb) * 512 + (CH) * 64 + kc;   \
        const float* _x1 = _x0 + (size_t)64 * 512;                         \
        const float* _w  = Wih + (size_t)grow_of(Nb + lb) * 512 + (CH) * 64 + kc; \
        _Pragma("unroll")                                                  \
        for (int _c = 0; _c < 4; ++_c) {                                   \
            pa[_c]     = *(const float4*)(_x0 + _c * 16);                  \
            pa[4 + _c] = *(const float4*)(_x1 + _c * 16);                  \
            pb[_c]     = *(const float4*)(_w  + _c * 16);                  \
        }                                                                  \
    } while (0)
#define CVT4(F) make_uint4(to_tf32((F).x), to_tf32((F).y), to_tf32((F).z), to_tf32((F).w))
#define STOREX() do {                                                      \
        unsigned* _da0 = (unsigned*)At + lb * 68 + kc;                     \
        unsigned* _da1 = (unsigned*)At + (64 + lb) * 68 + kc;              \
        unsigned* _db  = (unsigned*)Bt + lb * 68 + kc;                     \
        _Pragma("unroll")                                                  \
        for (int _c = 0; _c < 4; ++_c) {                                   \
            *(uint4*)(_da0 + _c * 16) = CVT4(pa[_c]);                      \
            *(uint4*)(_da1 + _c * 16) = CVT4(pa[4 + _c]);                  \
            *(uint4*)(_db  + _c * 16) = CVT4(pb[_c]);                      \
        }                                                                  \
    } while (0)

    LOADX(0);
    STOREX();
    __syncthreads();

    for (int ch = 0; ch < 8; ++ch) {
        const bool more = (ch + 1 < 8);
        if (more) LOADX(ch + 1);

        const unsigned* A = (const unsigned*)At;
        const unsigned* B = (const unsigned*)Bt;
#pragma unroll
        for (int i = 0; i < 8; ++i) {
            const int ka = i * 8 + (lane & 3);
            unsigned a[2][4];
#pragma unroll
            for (int m2 = 0; m2 < 2; ++m2) {
                int rb = mw * 32 + m2 * 16 + (lane >> 2);
                a[m2][0] = A[rb * 68 + ka];
                a[m2][1] = A[(rb + 8) * 68 + ka];
                a[m2][2] = A[rb * 68 + ka + 4];
                a[m2][3] = A[(rb + 8) * 68 + ka + 4];
            }
#pragma unroll
            for (int nt = 0; nt < 4; ++nt) {
                int nb = nw * 32 + nt * 8 + (lane >> 2);
                unsigned b0 = B[nb * 68 + ka];
                unsigned b1 = B[nb * 68 + ka + 4];
                mma_tf32(acc[0][nt], a[0][0], a[0][1], a[0][2], a[0][3], b0, b1);
                mma_tf32(acc[1][nt], a[1][0], a[1][1], a[1][2], a[1][3], b0, b1);
            }
        }
        __syncthreads();
        if (more) {
            STOREX();
            __syncthreads();
        }
    }
#undef LOADX
#undef STOREX
#undef CVT4

    // scatter C -> xp[t][ct][b][r]
#pragma unroll
    for (int m2 = 0; m2 < 2; ++m2) {
#pragma unroll
        for (int nt = 0; nt < 4; ++nt) {
            int row0 = Mb + mw * 32 + m2 * 16 + (lane >> 2);
            int n    = Nb + nw * 32 + nt * 8 + 2 * (lane & 3);
            int t = row0 >> 6, b = row0 & 63;
            size_t idx = (((size_t)t * 128 + (n >> 4)) * 64 + b) * 16 + (n & 15);
            *(float2*)(g_xp + idx)       = make_float2(acc[m2][nt][0], acc[m2][nt][1]);
            *(float2*)(g_xp + idx + 128) = make_float2(acc[m2][nt][2], acc[m2][nt][3]);
        }
    }
}

// ======================= Phase 2: persistent recurrence =======================
// SMEM float offsets
#define HB_OFF   0                      // 8 subtiles x 64 x 68 = 34816
#define RED_OFF  34816                  // 8 x 1536 = 12288
#define BSM_OFF  (RED_OFF + 12288)      // 16
#define SB_OFF   (BSM_OFF + 16)         // ull base0 (8B aligned)
#define SM2_FLOATS (SB_OFF + 4)

__global__ __launch_bounds__(512, 1)
void lstm_rec(const float* __restrict__ Whh,
              const float* __restrict__ bih,
              const float* __restrict__ bhh,
              float* __restrict__ out)
{
    extern __shared__ float sm[];
    float* Hb  = sm + HB_OFF;
    float* Red = sm + RED_OFF;
    float* bsm = sm + BSM_OFF;
    unsigned long long* sbase = (unsigned long long*)(sm + SB_OFF);

    const int tid  = threadIdx.x;
    const int lane = tid & 31;
    const int wid  = tid >> 5;
    const int ct   = blockIdx.x;
    const int mt   = wid & 1;          // batches mt*32..+31
    const int ks   = wid >> 1;         // k subtile 0..7 (64 k each)

    // h staging mapping (512 threads cover 64 x 512)
    const int hb2 = tid >> 8;
    const int lb  = (tid & 255) >> 2;
    const int kc  = (tid & 3) * 4;

    // epilogue mapping (tid < 256)
    const int eb = tid >> 2;
    const int eu = tid & 3;
    float c_state = 0.0f;

    // ---- one-time: Whh B-fragments -> REGISTERS (weight-stationary) ----
    unsigned wreg[8][2][2];
#pragma unroll
    for (int i = 0; i < 8; ++i) {
#pragma unroll
        for (int nt = 0; nt < 2; ++nt) {
            int r = nt * 8 + (lane >> 2);
            int grow = (r & 3) * HDIM + ct * 4 + (r >> 2);
            int k0 = ks * 64 + i * 8 + (lane & 3);
            wreg[i][nt][0] = to_tf32(Whh[(size_t)grow * 512 + k0]);
            wreg[i][nt][1] = to_tf32(Whh[(size_t)grow * 512 + k0 + 4]);
        }
    }
    if (tid < 16) {
        int grow = (tid & 3) * HDIM + ct * 4 + (tid >> 2);
        bsm[tid] = bih[grow] + bhh[grow];
    }
    if (tid == 0) *sbase = ld_acquire(&g_cnt);
    __syncthreads();
    const unsigned long long base0 = *sbase;

    float* hout = out;
    float* cout = out + (size_t)S_LEN * NBATCH * HDIM;

    for (int t = 0; t < S_LEN; ++t) {
        // prefetch x-projection slice (independent of h)
        float4 xpv;
        if (tid < 256)
            xpv = *(const float4*)(g_xp + (((size_t)t * 128 + ct) * 64 + eb) * 16 + eu * 4);

        if (t > 0) {
            // one-hop acquire barrier: all 128 release-arrivals of step t-1 seen
            if (tid == 0) {
                const unsigned long long target = base0 + (unsigned long long)NCTA * t;
                while (ld_acquire(&g_cnt) < target) { }
            }
            __syncthreads();

            // ---- stage full h_{t-1}: 8 subtiles of 64x64, stride 68, tf32 ----
            const float* hbase = hout + (size_t)(t - 1) * (NBATCH * HDIM);
#pragma unroll
            for (int i = 0; i < 4; ++i) {
                int st = hb2 * 4 + i;
                const float* sp = hbase + (size_t)lb * 512 + st * 64 + kc;
                unsigned* dp = (unsigned*)(Hb + st * 4352) + lb * 68 + kc;
#pragma unroll
                for (int c4 = 0; c4 < 4; ++c4) {
                    float4 f = *(const float4*)(sp + c4 * 16);
                    *(uint4*)(dp + c4 * 16) = make_uint4(to_tf32(f.x), to_tf32(f.y),
                                                         to_tf32(f.z), to_tf32(f.w));
                }
            }
            __syncthreads();

            // ---- h GEMM: warp (mt, ks); W from registers ----
            float acc[2][2][4];    // [m2][nt][4]
#pragma unroll
            for (int m2 = 0; m2 < 2; ++m2)
#pragma unroll
                for (int nt = 0; nt < 2; ++nt)
#pragma unroll
                    for (int q = 0; q < 4; ++q) acc[m2][nt][q] = 0.f;

            const unsigned* Ab = (const unsigned*)(Hb + ks * 4352);
#pragma unroll
            for (int i = 0; i < 8; ++i) {
                const int ka = i * 8 + (lane & 3);
#pragma unroll
                for (int m2 = 0; m2 < 2; ++m2) {
                    const int ra = mt * 32 + m2 * 16 + (lane >> 2);
                    unsigned a0 = Ab[ra * 68 + ka];
                    unsigned a1 = Ab[(ra + 8) * 68 + ka];
                    unsigned a2 = Ab[ra * 68 + ka + 4];
                    unsigned a3 = Ab[(ra + 8) * 68 + ka + 4];
                    mma_tf32(acc[m2][0], a0, a1, a2, a3, wreg[i][0][0], wreg[i][0][1]);
                    mma_tf32(acc[m2][1], a0, a1, a2, a3, wreg[i][1][0], wreg[i][1][1]);
                }
            }

            // partials -> Red[ks] : [64][24]
            float* Rp = Red + ks * 1536;
#pragma unroll
            for (int m2 = 0; m2 < 2; ++m2) {
                const int rr = mt * 32 + m2 * 16 + (lane >> 2);
#pragma unroll
                for (int nt = 0; nt < 2; ++nt) {
                    const int cc = nt * 8 + 2 * (lane & 3);
                    *(float2*)(Rp + rr * 24 + cc) =
                        make_float2(acc[m2][nt][0], acc[m2][nt][1]);
                    *(float2*)(Rp + (rr + 8) * 24 + cc) =
                        make_float2(acc[m2][nt][2], acc[m2][nt][3]);
                }
            }
        }

        __syncthreads();

        if (tid < 256) {
            float g[4];
#pragma unroll
            for (int j = 0; j < 4; ++j) g[j] = bsm[eu * 4 + j];
            g[0] += xpv.x; g[1] += xpv.y; g[2] += xpv.z; g[3] += xpv.w;
            if (t > 0) {
#pragma unroll
                for (int s = 0; s < 8; ++s) {
                    const float4 p = *(const float4*)(Red + s * 1536 + eb * 24 + eu * 4);
                    g[0] += p.x; g[1] += p.y; g[2] += p.z; g[3] += p.w;
                }
            }
            float gi = fast_sigmoid(g[0]);
            float gf = fast_sigmoid(g[1]);
            float gg = fast_tanh  (g[2]);
            float go = fast_sigmoid(g[3]);
            c_state = gf * c_state + gi * gg;
            float hval = go * fast_tanh(c_state);

            size_t o = (size_t)t * (NBATCH * HDIM) + (size_t)eb * HDIM + ct * 4 + eu;
            hout[o] = hval;
            cout[o] = c_state;
        }

        __syncthreads();   // intra-CTA hb: all h/c stores precede the arrive

        // release-arrive (one hop; wait is the acquire poll at step t+1)
        if (tid == 0) bar_arrive_release(&g_cnt);
    }
}

extern "C" void kernel_launch(void* const* d_in, const int* in_sizes, int n_in,
                              void* d_out, int out_size)
{
    const float* x   = (const float*)d_in[0];
    const float* Wih = (const float*)d_in[1];
    const float* Whh = (const float*)d_in[2];
    const float* bih = (const float*)d_in[3];
    const float* bhh = (const float*)d_in[4];
    float* out = (float*)d_out;

    const int sm1_bytes = (128 * 68 + 64 * 68) * 4;  // 52.2 KB -> 2 CTAs/SM
    cudaFuncSetAttribute(lstm_xproj,
                         cudaFuncAttributeMaxDynamicSharedMemorySize, sm1_bytes);
    const int sm2_bytes = SM2_FLOATS * 4;            // ~188.5 KB -> 1 CTA/SM
    cudaFuncSetAttribute(lstm_rec,
                         cudaFuncAttributeMaxDynamicSharedMemorySize, sm2_bytes);

    lstm_xproj<<<32768, 256, sm1_bytes>>>(x, Wih);
    lstm_rec<<<NCTA, 512, sm2_bytes>>>(Whh, bih, bhh, out);
}

// round 17
// speedup vs baseline: 1.9708x; 1.9708x over previous
#include <cuda_runtime.h>
#include <cstdint>

#define S_LEN    2048
#define NBATCH   64
#define DIN      512
#define HDIM     512
#define NCTA     128

// ---- 1 GB x-projection scratch: xp[t][ctg(64)][b(64)][u*4+g (32)] ----
__device__ float g_xp[(size_t)S_LEN * 64 * 64 * 32];

// monotonic grid-barrier counter (64-bit: no wrap across replays)
__device__ unsigned long long g_cnt = 0;

__device__ __forceinline__ float fast_sigmoid(float x) {
    return 1.0f / (1.0f + __expf(-x));
}
__device__ __forceinline__ float fast_tanh(float x) {
    float ax = fabsf(x);
    float e  = __expf(-2.0f * ax);
    return copysignf((1.0f - e) / (1.0f + e), x);
}
__device__ __forceinline__ unsigned to_tf32(float f) {
    unsigned r;
    asm("cvt.rna.tf32.f32 %0, %1;" : "=r"(r) : "f"(f));
    return r;
}
__device__ __forceinline__ void mma_tf32(float* c, unsigned a0, unsigned a1,
                                         unsigned a2, unsigned a3,
                                         unsigned b0, unsigned b1) {
    asm("mma.sync.aligned.m16n8k8.row.col.f32.tf32.tf32.f32 "
        "{%0,%1,%2,%3}, {%4,%5,%6,%7}, {%8,%9}, {%0,%1,%2,%3};"
        : "+f"(c[0]), "+f"(c[1]), "+f"(c[2]), "+f"(c[3])
        : "r"(a0), "r"(a1), "r"(a2), "r"(a3), "r"(b0), "r"(b1));
}

// gate-row scatter: n in [0,2048) -> W row.
// n = ctg*32 + u*4 + g  ->  W row = g*512 + ctg*8 + u
__device__ __forceinline__ int grow_of(int n) {
    return (n & 3) * HDIM + (n >> 5) * 8 + ((n >> 2) & 7);
}

// ======================= Phase 1: xp = x @ W_ih^T (R11 structure) ============
__global__ __launch_bounds__(256, 2)
void lstm_xproj(const float* __restrict__ x, const float* __restrict__ Wih)
{
    extern __shared__ float sm1[];
    float* At = sm1;              // 128 x 68
    float* Bt = sm1 + 128 * 68;   // 128 x 68

    const int tid  = threadIdx.x;
    const int lane = tid & 31;
    const int w    = tid >> 5;
    const int mw   = w & 3;
    const int nw   = w >> 2;
    const int ntile = blockIdx.x & 15;
    const int mtile = blockIdx.x >> 4;
    const int Mb = mtile * 128, Nb = ntile * 128;

    const int lb = tid >> 2;
    const int kc = (tid & 3) * 4;

    float acc[2][8][4];
#pragma unroll
    for (int a = 0; a < 2; ++a)
#pragma unroll
        for (int b = 0; b < 8; ++b)
#pragma unroll
            for (int q = 0; q < 4; ++q) acc[a][b][q] = 0.f;

    for (int ch = 0; ch < 8; ++ch) {
        __syncthreads();
#pragma unroll
        for (int p = 0; p < 2; ++p) {
            int row = p * 64 + lb;
            const float* xs = x + (size_t)(Mb + row) * 512 + ch * 64 + kc;
            unsigned* da = (unsigned*)At + row * 68 + kc;
            int n = Nb + row;
            const float* ws = Wih + (size_t)grow_of(n) * 512 + ch * 64 + kc;
            unsigned* db = (unsigned*)Bt + row * 68 + kc;
#pragma unroll
            for (int c4 = 0; c4 < 4; ++c4) {
                float4 f = *(const float4*)(xs + c4 * 16);
                *(uint4*)(da + c4 * 16) = make_uint4(to_tf32(f.x), to_tf32(f.y),
                                                     to_tf32(f.z), to_tf32(f.w));
                float4 g = *(const float4*)(ws + c4 * 16);
                *(uint4*)(db + c4 * 16) = make_uint4(to_tf32(g.x), to_tf32(g.y),
                                                     to_tf32(g.z), to_tf32(g.w));
            }
        }
        __syncthreads();

        const unsigned* A = (const unsigned*)At;
        const unsigned* B = (const unsigned*)Bt;
#pragma unroll
        for (int i = 0; i < 8; ++i) {
            const int ka = i * 8 + (lane & 3);
            unsigned a[2][4];
#pragma unroll
            for (int m2 = 0; m2 < 2; ++m2) {
                int rb = mw * 32 + m2 * 16 + (lane >> 2);
                a[m2][0] = A[rb * 68 + ka];
                a[m2][1] = A[(rb + 8) * 68 + ka];
                a[m2][2] = A[rb * 68 + ka + 4];
                a[m2][3] = A[(rb + 8) * 68 + ka + 4];
            }
#pragma unroll
            for (int nt = 0; nt < 8; ++nt) {
                int nb = nw * 64 + nt * 8 + (lane >> 2);
                unsigned b0 = B[nb * 68 + ka];
                unsigned b1 = B[nb * 68 + ka + 4];
                mma_tf32(acc[0][nt], a[0][0], a[0][1], a[0][2], a[0][3], b0, b1);
                mma_tf32(acc[1][nt], a[1][0], a[1][1], a[1][2], a[1][3], b0, b1);
            }
        }
    }

    // scatter C -> xp[t][ctg][b][n&31]   (n = Nb + ..., float2 pairs contiguous)
#pragma unroll
    for (int m2 = 0; m2 < 2; ++m2) {
#pragma unroll
        for (int nt = 0; nt < 8; ++nt) {
            int row0 = Mb + mw * 32 + m2 * 16 + (lane >> 2);
            int n    = Nb + nw * 64 + nt * 8 + 2 * (lane & 3);
            int t = row0 >> 6, b = row0 & 63;
            size_t idx = (((size_t)t * 64 + (n >> 5)) * 64 + b) * 32 + (n & 31);
            *(float2*)(g_xp + idx)       = make_float2(acc[m2][nt][0], acc[m2][nt][1]);
            *(float2*)(g_xp + idx + 256) = make_float2(acc[m2][nt][2], acc[m2][nt][3]);
            // +256 = (b+8)*32: c2/c3 live at batch row b+8, same (t, ctg, n&31)
        }
    }
}

// ======================= Phase 2: persistent recurrence =======================
// CTA = (ctg, p): hidden units ctg*8..+7, batches p*32..+31.
// SMEM float offsets
#define HB_OFF   0                      // 8 subtiles x 32 x 68 = 17408
#define RED_OFF  17408                  // 8 x (32 x 36) = 9216
#define BSM_OFF  (RED_OFF + 9216)       // 32
#define SB_OFF   (BSM_OFF + 32)         // ull base0 (8B aligned)
#define SM2_FLOATS (SB_OFF + 4)

__global__ __launch_bounds__(512, 1)
void lstm_rec(const float* __restrict__ Whh,
              const float* __restrict__ bih,
              const float* __restrict__ bhh,
              float* __restrict__ out)
{
    extern __shared__ float sm[];
    float* Hb  = sm + HB_OFF;
    float* Red = sm + RED_OFF;
    float* bsm = sm + BSM_OFF;
    unsigned long long* sbase = (unsigned long long*)(sm + SB_OFF);

    const int tid  = threadIdx.x;
    const int lane = tid & 31;
    const int wid  = tid >> 5;
    const int ctg  = blockIdx.x >> 1;   // column group: units ctg*8..+7
    const int p    = blockIdx.x & 1;    // batch half: batches p*32..+31
    const int nh   = wid & 1;           // gate-row half: local rows nh*16..+15
    const int ks   = wid >> 1;          // k subtile 0..7 (64 k each)

    // staging mapping: 512 threads cover 32 rows x 512 cols (8 subtiles)
    const int srow = tid >> 4;          // 0..31
    const int skc  = (tid & 15) * 4;    // float4 col within subtile

    // epilogue mapping (tid < 256): local batch bl, local unit u
    const int bl = tid >> 3;            // 0..31
    const int u  = tid & 7;             // 0..7
    float c_state = 0.0f;

    // ---- one-time: Whh B-fragments -> REGISTERS (weight-stationary) ----
    // warp (ks, nh): local gate rows r = nh*16 + nt*8 + (lane>>2); r = u*4+g
    unsigned wreg[8][2][2];
#pragma unroll
    for (int i = 0; i < 8; ++i) {
#pragma unroll
        for (int nt = 0; nt < 2; ++nt) {
            int r = nh * 16 + nt * 8 + (lane >> 2);
            int grow = (r & 3) * HDIM + ctg * 8 + (r >> 2);
            int k0 = ks * 64 + i * 8 + (lane & 3);
            wreg[i][nt][0] = to_tf32(Whh[(size_t)grow * 512 + k0]);
            wreg[i][nt][1] = to_tf32(Whh[(size_t)grow * 512 + k0 + 4]);
        }
    }
    if (tid < 32) {
        int grow = (tid & 3) * HDIM + ctg * 8 + (tid >> 2);
        bsm[tid] = bih[grow] + bhh[grow];
    }
    if (tid == 0) *sbase = *((volatile unsigned long long*)&g_cnt);
    __syncthreads();
    const unsigned long long base0 = *sbase;

    float* hout = out;
    float* cout = out + (size_t)S_LEN * NBATCH * HDIM;

    for (int t = 0; t < S_LEN; ++t) {
        // prefetch x-projection slice (independent of h)
        float4 xpv;
        if (tid < 256)
            xpv = *(const float4*)(g_xp +
                    (((size_t)t * 64 + ctg) * 64 + (p * 32 + bl)) * 32 + u * 4);

        if (t > 0) {
            // one-hop barrier wait (volatile poll; writers fenced)
            if (tid == 0) {
                const unsigned long long target = base0 + (unsigned long long)NCTA * t;
                while (*((volatile unsigned long long*)&g_cnt) < target) { }
            }
            __syncthreads();

            // ---- stage this CTA's h half: 32 rows x 512, 8 subtiles [32][68] ----
            const float* hbase = hout + (size_t)(t - 1) * (NBATCH * HDIM)
                                 + (size_t)(p * 32 + srow) * 512 + skc;
            unsigned* dbase = (unsigned*)Hb + srow * 68 + skc;
#pragma unroll
            for (int st = 0; st < 8; ++st) {
                float4 f = *(const float4*)(hbase + st * 64);
                *(uint4*)(dbase + st * 2176) = make_uint4(to_tf32(f.x), to_tf32(f.y),
                                                          to_tf32(f.z), to_tf32(f.w));
            }
            __syncthreads();

            // ---- h GEMM: warp (ks, nh); W from registers ----
            float acc[2][2][4];    // [m2][nt][4]
#pragma unroll
            for (int m2 = 0; m2 < 2; ++m2)
#pragma unroll
                for (int nt = 0; nt < 2; ++nt)
#pragma unroll
                    for (int q = 0; q < 4; ++q) acc[m2][nt][q] = 0.f;

            const unsigned* Ab = (const unsigned*)(Hb + ks * 2176);
#pragma unroll
            for (int i = 0; i < 8; ++i) {
                const int ka = i * 8 + (lane & 3);
#pragma unroll
                for (int m2 = 0; m2 < 2; ++m2) {
                    const int ra = m2 * 16 + (lane >> 2);   // local batch row
                    unsigned a0 = Ab[ra * 68 + ka];
                    unsigned a1 = Ab[(ra + 8) * 68 + ka];
                    unsigned a2 = Ab[ra * 68 + ka + 4];
                    unsigned a3 = Ab[(ra + 8) * 68 + ka + 4];
                    mma_tf32(acc[m2][0], a0, a1, a2, a3, wreg[i][0][0], wreg[i][0][1]);
                    mma_tf32(acc[m2][1], a0, a1, a2, a3, wreg[i][1][0], wreg[i][1][1]);
                }
            }

            // partials -> Red[ks] : [32][36]
            float* Rp = Red + ks * 1152;
#pragma unroll
            for (int m2 = 0; m2 < 2; ++m2) {
                const int rr = m2 * 16 + (lane >> 2);
#pragma unroll
                for (int nt = 0; nt < 2; ++nt) {
                    const int cc = nh * 16 + nt * 8 + 2 * (lane & 3);
                    *(float2*)(Rp + rr * 36 + cc) =
                        make_float2(acc[m2][nt][0], acc[m2][nt][1]);
                    *(float2*)(Rp + (rr + 8) * 36 + cc) =
                        make_float2(acc[m2][nt][2], acc[m2][nt][3]);
                }
            }
        }

        __syncthreads();   // all 8 Red slices ready

        if (tid < 256) {
            float g[4];
#pragma unroll
            for (int j = 0; j < 4; ++j) g[j] = bsm[u * 4 + j];
            g[0] += xpv.x; g[1] += xpv.y; g[2] += xpv.z; g[3] += xpv.w;
            if (t > 0) {
#pragma unroll
                for (int s = 0; s < 8; ++s) {
                    const float4 pr = *(const float4*)(Red + s * 1152 + bl * 36 + u * 4);
                    g[0] += pr.x; g[1] += pr.y; g[2] += pr.z; g[3] += pr.w;
                }
            }
            float gi = fast_sigmoid(g[0]);
            float gf = fast_sigmoid(g[1]);
            float gg = fast_tanh  (g[2]);
            float go = fast_sigmoid(g[3]);
            c_state = gf * c_state + gi * gg;
            float hval = go * fast_tanh(c_state);

            size_t o = (size_t)t * (NBATCH * HDIM)
                       + (size_t)(p * 32 + bl) * 512 + ctg * 8 + u;
            hout[o] = hval;
            cout[o] = c_state;
            __threadfence();   // parallel per-writer drain
        }

        __syncthreads();   // h_t written + fenced by all writers

        // relaxed arrive (one hop; wait is the poll at step t+1)
        if (tid == 0) atomicAdd(&g_cnt, 1ULL);
    }
}

extern "C" void kernel_launch(void* const* d_in, const int* in_sizes, int n_in,
                              void* d_out, int out_size)
{
    const float* x   = (const float*)d_in[0];
    const float* Wih = (const float*)d_in[1];
    const float* Whh = (const float*)d_in[2];
    const float* bih = (const float*)d_in[3];
    const float* bhh = (const float*)d_in[4];
    float* out = (float*)d_out;

    const int sm1_bytes = 2 * 128 * 68 * 4;          // 69.6 KB
    cudaFuncSetAttribute(lstm_xproj,
                         cudaFuncAttributeMaxDynamicSharedMemorySize, sm1_bytes);
    // ~104.2 KB used; request 120 KB so 2 CTAs never share an SM
    // (guarantees all 128 persistent CTAs co-resident at 1/SM for the barrier).
    const int sm2_bytes = 120 * 1024;
    cudaFuncSetAttribute(lstm_rec,
                         cudaFuncAttributeMaxDynamicSharedMemorySize, sm2_bytes);

    lstm_xproj<<<16384, 256, sm1_bytes>>>(x, Wih);
    lstm_rec<<<NCTA, 512, sm2_bytes>>>(Whh, bih, bhh, out);
}